// round 14
// baseline (speedup 1.0000x reference)
#include <cuda_runtime.h>
#include <cuda_fp16.h>
#include <cstdint>

// Problem constants
constexpr int CB = 4;      // batch
constexpr int CN = 2048;   // query seq
constexpr int CM = 2048;   // context seq
constexpr int CC = 1024;   // channels
constexpr int CH = 16;     // heads
constexpr int CD = 64;     // head dim

// Scratch (device globals: allocation-free rule)
__device__ float g_q[(size_t)CB * CN * CC];          // 32 MB
__device__ float g_kv[(size_t)CB * CM * 2 * CC];     // 64 MB

// fp16 K (single, rope'd) and V (2-term split, transposed [b][h][d][m])
constexpr size_t KV_U4 = (size_t)CB * CH * CM * CD / 8;
__device__ uint4 g_kh[KV_U4];
__device__ uint4 g_vhi[KV_U4];
__device__ uint4 g_vlo[KV_U4];

// fp16-split activation operand (x -> ctx -> attn): hi+lo
constexpr size_t ACT_U4 = (size_t)CB * CN * CC / 8;
__device__ uint4 g_ahi[ACT_U4];
__device__ uint4 g_alo[ACT_U4];
// fp16 single weight operand (Wq -> Wkv -> Wproj)
constexpr size_t W_U4 = (size_t)2 * CC * CC / 8;
__device__ uint4 g_wh[W_U4];

// ============================================================================
// mma.sync m16n8k16 f16 -> f32, ldmatrix
// ============================================================================
__device__ __forceinline__ void mma16816(float* d,
    uint32_t a0, uint32_t a1, uint32_t a2, uint32_t a3,
    uint32_t b0, uint32_t b1)
{
    asm volatile(
        "mma.sync.aligned.m16n8k16.row.col.f32.f16.f16.f32 "
        "{%0,%1,%2,%3}, {%4,%5,%6,%7}, {%8,%9}, {%0,%1,%2,%3};"
        : "+f"(d[0]), "+f"(d[1]), "+f"(d[2]), "+f"(d[3])
        : "r"(a0), "r"(a1), "r"(a2), "r"(a3), "r"(b0), "r"(b1));
}

__device__ __forceinline__ void ldmatrix_x4(
    uint32_t& r0, uint32_t& r1, uint32_t& r2, uint32_t& r3, uint32_t addr)
{
    asm volatile(
        "ldmatrix.sync.aligned.m8n8.x4.shared.b16 {%0,%1,%2,%3}, [%4];"
        : "=r"(r0), "=r"(r1), "=r"(r2), "=r"(r3) : "r"(addr));
}

__device__ __forceinline__ uint32_t pack2h(float x, float y) {
    __half2 t = __floats2half2_rn(x, y);
    return *(uint32_t*)&t;
}
__device__ __forceinline__ void split2h(float x, float y, uint32_t& h, uint32_t& l) {
    __half hx = __float2half_rn(x);
    __half hy = __float2half_rn(y);
    float rx = x - __half2float(hx);
    float ry = y - __half2float(hy);
    __half2 th = __halves2half2(hx, hy);
    __half2 tl = __halves2half2(__float2half_rn(rx), __float2half_rn(ry));
    h = *(uint32_t*)&th;
    l = *(uint32_t*)&tl;
}

// 8 floats -> packed hi/lo fp16 (uint4 each)
__device__ __forceinline__ void cvt8_split(const float* g, uint4& hi, uint4& lo) {
    float4 a = *(const float4*)g;
    float4 b = *(const float4*)(g + 4);
    uint32_t* ph = (uint32_t*)&hi;
    uint32_t* pl = (uint32_t*)&lo;
    split2h(a.x, a.y, ph[0], pl[0]);
    split2h(a.z, a.w, ph[1], pl[1]);
    split2h(b.x, b.y, ph[2], pl[2]);
    split2h(b.z, b.w, ph[3], pl[3]);
}
// 8 floats -> packed fp16 (uint4)
__device__ __forceinline__ uint4 cvt8h(const float* g) {
    float4 a = *(const float4*)g;
    float4 b = *(const float4*)(g + 4);
    uint4 r;
    r.x = pack2h(a.x, a.y); r.y = pack2h(a.z, a.w);
    r.z = pack2h(b.x, b.y); r.w = pack2h(b.z, b.w);
    return r;
}

__device__ __forceinline__ uint32_t smem_u32(const void* p) {
    uint32_t a;
    asm("{ .reg .u64 t; cvta.to.shared.u64 t, %1; cvt.u32.u64 %0, t; }"
        : "=r"(a) : "l"(p));
    return a;
}
__device__ __forceinline__ void cp_async16(uint32_t dst, const void* src) {
    asm volatile("cp.async.cg.shared.global [%0], [%1], 16;"
                 :: "r"(dst), "l"(src) : "memory");
}
__device__ __forceinline__ void cp_commit() {
    asm volatile("cp.async.commit_group;" ::: "memory");
}
__device__ __forceinline__ void cp_wait1() {
    asm volatile("cp.async.wait_group 1;" ::: "memory");
}

// ============================================================================
// split_kernel: fp32[n] -> fp16 hi[n], lo[n].   cvt_kernel: fp32 -> fp16.
// ============================================================================
__global__ void __launch_bounds__(256) split_kernel(
    const float* __restrict__ src, uint4* __restrict__ hi,
    uint4* __restrict__ lo, int n8)
{
    int i = blockIdx.x * blockDim.x + threadIdx.x;
    if (i >= n8) return;
    uint4 h, l;
    cvt8_split(src + (size_t)i * 8, h, l);
    hi[i] = h;
    lo[i] = l;
}

__global__ void __launch_bounds__(256) cvt_kernel(
    const float* __restrict__ src, uint4* __restrict__ dst, int n8)
{
    int i = blockIdx.x * blockDim.x + threadIdx.x;
    if (i >= n8) return;
    dst[i] = cvt8h(src + (size_t)i * 8);
}

// ============================================================================
// NT GEMM: C[M,N] = A[M,K] * B[N,K]^T (+bias). A = fp16 hi+lo, B = fp16.
// 2-term emulation. CTA 128x128, 4 warps (2m x 2n, warp 64x64), BK=32,
// double-buffered cp.async, ldmatrix. 25% fewer LDS bytes per HMMA vs 32x64.
// ============================================================================
constexpr int GS = 20;                  // words per smem row (16 data + 4 pad)
constexpr int GT_TSZ = 128 * GS;        // words per tile (2560)
constexpr int GBUF = 3 * GT_TSZ;        // Ahi, Alo, B
constexpr int GEMM_SMEM = 2 * GBUF * 4; // 61440 bytes

__global__ void __launch_bounds__(128) gemm_fp16_kernel(
    const __half* __restrict__ Ahi, const __half* __restrict__ Alo,
    const __half* __restrict__ Bh,
    float* __restrict__ C, int M, int N, int K, const float* __restrict__ bias)
{
    extern __shared__ uint32_t gsm[];
    const uint32_t smb = smem_u32(gsm);

    const int tid = threadIdx.x;
    const int wid = tid >> 5;            // 0..3
    const int lane = tid & 31;
    const int warp_m = wid & 1;          // 2 x 64 rows
    const int warp_n = wid >> 1;         // 2 x 64 cols
    const int m0 = blockIdx.y * 128;
    const int n0 = blockIdx.x * 128;

    const int lrow16 = lane & 15;
    const int lhiA   = (lane >> 4) * 4;
    const int browB  = ((lane >> 4) & 1) * 8 + (lane & 7);
    const int bkB    = ((lane >> 3) & 1) * 4;

    float acc[4][8][4];
#pragma unroll
    for (int i = 0; i < 4; i++)
#pragma unroll
        for (int j = 0; j < 8; j++)
#pragma unroll
            for (int q = 0; q < 4; q++) acc[i][j][q] = 0.f;

    // loader: 128 threads, 1 row each, 4 chunks x 3 tiles.
    auto issue = [&](int kc, int buf) {
        const int k0 = kc * 32;
        const uint32_t base = smb + buf * GBUF * 4;
#pragma unroll
        for (int c = 0; c < 4; c++) {
            uint32_t so = base + (tid * GS + c * 4) * 4;
            size_t aof = ((size_t)(m0 + tid) * K + k0 + c * 8) * 2;
            size_t bof = ((size_t)(n0 + tid) * K + k0 + c * 8) * 2;
            cp_async16(so,                  (const char*)Ahi + aof);
            cp_async16(so + GT_TSZ * 4,     (const char*)Alo + aof);
            cp_async16(so + 2 * GT_TSZ * 4, (const char*)Bh + bof);
        }
    };

    const int niter = K / 32;
    issue(0, 0);
    cp_commit();

    for (int kc = 0; kc < niter; kc++) {
        int buf = kc & 1;
        if (kc + 1 < niter) issue(kc + 1, buf ^ 1);
        cp_commit();
        cp_wait1();
        __syncthreads();

        const uint32_t aAhi = smb + buf * GBUF * 4;
        const uint32_t aAlo = aAhi + GT_TSZ * 4;
        const uint32_t aB   = aAhi + 2 * GT_TSZ * 4;

#pragma unroll
        for (int ks = 0; ks < 2; ks++) {
            uint32_t ah[4][4], al[4][4];
#pragma unroll
            for (int i = 0; i < 4; i++) {
                uint32_t off = ((warp_m * 64 + i * 16 + lrow16) * GS + ks * 8 + lhiA) * 4;
                ldmatrix_x4(ah[i][0], ah[i][1], ah[i][2], ah[i][3], aAhi + off);
                ldmatrix_x4(al[i][0], al[i][1], al[i][2], al[i][3], aAlo + off);
            }
#pragma unroll
            for (int jp = 0; jp < 4; jp++) {
                uint32_t b0, b1, b2, b3;
                uint32_t bd = aB + ((warp_n * 64 + jp * 16 + browB) * GS + ks * 8 + bkB) * 4;
                ldmatrix_x4(b0, b1, b2, b3, bd);
#pragma unroll
                for (int i = 0; i < 4; i++) {
                    mma16816(acc[i][2*jp],   ah[i][0], ah[i][1], ah[i][2], ah[i][3], b0, b1);
                    mma16816(acc[i][2*jp],   al[i][0], al[i][1], al[i][2], al[i][3], b0, b1);
                    mma16816(acc[i][2*jp+1], ah[i][0], ah[i][1], ah[i][2], ah[i][3], b2, b3);
                    mma16816(acc[i][2*jp+1], al[i][0], al[i][1], al[i][2], al[i][3], b2, b3);
                }
            }
        }
        __syncthreads();
    }

#pragma unroll
    for (int i = 0; i < 4; i++) {
        int row = m0 + warp_m * 64 + i * 16 + (lane >> 2);
#pragma unroll
        for (int j = 0; j < 8; j++) {
            int col = n0 + warp_n * 64 + j * 8 + (lane & 3) * 2;
            float2 w0, w1;
            w0.x = acc[i][j][0]; w0.y = acc[i][j][1];
            w1.x = acc[i][j][2]; w1.y = acc[i][j][3];
            if (bias) {
                float2 bb = *(const float2*)(bias + col);
                w0.x += bb.x; w0.y += bb.y;
                w1.x += bb.x; w1.y += bb.y;
            }
            *(float2*)(C + (size_t)row * N + col) = w0;
            *(float2*)(C + (size_t)(row + 8) * N + col) = w1;
        }
    }
}

// ----------------------------------------------------------------------------
// Convert pre-pass: K-RoPE + fp16 cvt (single); V fp16 split + transpose.
// ----------------------------------------------------------------------------
__global__ void __launch_bounds__(256) conv_kernel(const float* __restrict__ fc)
{
    __shared__ float sv[64][68];
    const int tid = threadIdx.x;
    const int blk = blockIdx.x, h = blockIdx.y, b = blockIdx.z;
    const int bh = b * CH + h;

    const int kl = tid >> 2;
    const int ch = tid & 3;
    const int m  = blk * 64 + kl;
    const int d0 = ch * 16;

    // ---- K: read, rope, cvt fp16, store [b][h][m][d] ----
    {
        const float* kp = g_kv + ((size_t)b * CM + m) * (2 * CC) + h * CD + d0;
        float v[16];
        *(float4*)(v + 0)  = *(const float4*)(kp + 0);
        *(float4*)(v + 4)  = *(const float4*)(kp + 4);
        *(float4*)(v + 8)  = *(const float4*)(kp + 8);
        *(float4*)(v + 12) = *(const float4*)(kp + 12);
        uint4 kk[2];
        uint32_t* pk = (uint32_t*)kk;
#pragma unroll
        for (int i = 0; i < 8; i++) {
            int d2 = ch * 8 + i;
            float2 f = *(const float2*)(fc + m * 64 + d2 * 2);
            float rx = v[2*i] * f.x - v[2*i+1] * f.y;
            float ry = v[2*i+1] * f.x + v[2*i] * f.y;
            pk[i] = pack2h(rx, ry);
        }
        size_t o = (((size_t)bh * CM + m) * CD + d0) / 8;
        g_kh[o] = kk[0]; g_kh[o + 1] = kk[1];
    }

    // ---- V: stage to smem, transpose, split fp16, store [b][h][d][m] ----
    {
        const float* vp = g_kv + ((size_t)b * CM + m) * (2 * CC) + CC + h * CD + d0;
        float4 a = *(const float4*)(vp + 0);
        float4 c = *(const float4*)(vp + 4);
        float4 e = *(const float4*)(vp + 8);
        float4 g = *(const float4*)(vp + 12);
        *(float4*)&sv[kl][d0 + 0]  = a;
        *(float4*)&sv[kl][d0 + 4]  = c;
        *(float4*)&sv[kl][d0 + 8]  = e;
        *(float4*)&sv[kl][d0 + 12] = g;
    }
    __syncthreads();
    {
        const int d  = tid >> 2;
        const int kc = tid & 3;
        uint4 hi[2], lo[2];
        uint32_t* ph = (uint32_t*)hi;
        uint32_t* pl = (uint32_t*)lo;
#pragma unroll
        for (int i = 0; i < 8; i++) {
            int key = kc * 16 + 2 * i;
            split2h(sv[key][d], sv[key + 1][d], ph[i], pl[i]);
        }
        size_t o = (((size_t)bh * CD + d) * CM + blk * 64 + kc * 16) / 8;
        g_vhi[o] = hi[0]; g_vhi[o + 1] = hi[1];
        g_vlo[o] = lo[0]; g_vlo[o + 1] = lo[1];
    }
}

// ----------------------------------------------------------------------------
// Tensor-core flash attention, fp16 2-term (Q split, K single; P single,
// V split). Q-RoPE fused. Epilogue writes fp16-split attn into g_ahi/g_alo.
// ----------------------------------------------------------------------------
constexpr int FT = 64 * 36;
constexpr int FBUF = 3 * FT;              // Kh, Vhi, Vlo
constexpr int FLASH_SMEM = 2 * FBUF * 4;  // 55296 bytes

__global__ void __launch_bounds__(256) flash_mma_kernel(
    const float* __restrict__ q, const float* __restrict__ fc)
{
    extern __shared__ uint32_t fsm[];
    const int tid  = threadIdx.x;
    const int wid  = tid >> 5;
    const int lane = tid & 31;
    const int gid  = lane >> 2;
    const int tig  = lane & 3;
    const int nt = blockIdx.x, h = blockIdx.y, b = blockIdx.z;
    const int bh = b * CH + h;

    const uint32_t smb = smem_u32(fsm);

    const int browB = ((lane >> 4) & 1) * 8 + (lane & 7);
    const int bkB   = ((lane >> 3) & 1) * 4;

    const int lrow8 = tid >> 3;
    const int lc8   = tid & 7;
    auto issue = [&](int jt, int buf) {
#pragma unroll
        for (int half = 0; half < 2; half++) {
            int row = lrow8 + half * 32;
            uint32_t so = smb + buf * (FBUF * 4) + (row * 36 + lc8 * 4) * 4;
            size_t kof = (((size_t)bh * CM + jt * 64 + row) * CD + lc8 * 8) * 2;
            size_t vof = (((size_t)bh * CD + row) * CM + jt * 64 + lc8 * 8) * 2;
            cp_async16(so,               (const char*)g_kh + kof);
            cp_async16(so + FT * 4,     (const char*)g_vhi + vof);
            cp_async16(so + 2 * FT * 4, (const char*)g_vlo + vof);
        }
    };

    issue(0, 0);
    cp_commit();

    // ---- Q fragments: rope + scale + fp16 split ----
    const float SCALE = 0.125f * 1.44269504088896340736f;
    uint32_t qh[4][4], ql[4][4];
    {
        const int n0_ = nt * 128 + wid * 16 + gid;
        const float* qr0 = q + ((size_t)b * CN + n0_) * CC + h * CD;
        const float* qr1 = qr0 + 8 * CC;
        const float* fc0 = fc + n0_ * 64;
        const float* fc1 = fc0 + 8 * 64;
#pragma unroll
        for (int ks = 0; ks < 4; ks++) {
            int c = ks * 16 + 2 * tig;
            int d2 = c >> 1;
            float2 f0a = *(const float2*)(fc0 + d2 * 2);
            float2 f0b = *(const float2*)(fc0 + (d2 + 4) * 2);
            float2 f1a = *(const float2*)(fc1 + d2 * 2);
            float2 f1b = *(const float2*)(fc1 + (d2 + 4) * 2);
            float2 x00 = *(const float2*)(qr0 + c);
            float2 x10 = *(const float2*)(qr1 + c);
            float2 x01 = *(const float2*)(qr0 + c + 8);
            float2 x11 = *(const float2*)(qr1 + c + 8);
            float r00x = x00.x * f0a.x - x00.y * f0a.y;
            float r00y = x00.y * f0a.x + x00.x * f0a.y;
            float r10x = x10.x * f1a.x - x10.y * f1a.y;
            float r10y = x10.y * f1a.x + x10.x * f1a.y;
            float r01x = x01.x * f0b.x - x01.y * f0b.y;
            float r01y = x01.y * f0b.x + x01.x * f0b.y;
            float r11x = x11.x * f1b.x - x11.y * f1b.y;
            float r11y = x11.y * f1b.x + x11.x * f1b.y;
            split2h(r00x * SCALE, r00y * SCALE, qh[ks][0], ql[ks][0]);
            split2h(r10x * SCALE, r10y * SCALE, qh[ks][1], ql[ks][1]);
            split2h(r01x * SCALE, r01y * SCALE, qh[ks][2], ql[ks][2]);
            split2h(r11x * SCALE, r11y * SCALE, qh[ks][3], ql[ks][3]);
        }
    }

    float o[8][4];
#pragma unroll
    for (int j = 0; j < 8; j++)
#pragma unroll
        for (int qi = 0; qi < 4; qi++) o[j][qi] = 0.f;
    float m0 = -1e30f, m1 = -1e30f, l0 = 0.f, l1 = 0.f;

    const int nblocks = CM / 64;
    for (int jt = 0; jt < nblocks; jt++) {
        int buf = jt & 1;
        if (jt + 1 < nblocks) issue(jt + 1, buf ^ 1);
        cp_commit();
        cp_wait1();
        __syncthreads();

        const uint32_t aKh = smb + buf * FBUF * 4;
        const uint32_t aVh = aKh + FT * 4;
        const uint32_t aVl = aKh + 2 * FT * 4;

        // ---- S = Q K^T (2-term) ----
        float s[8][4];
#pragma unroll
        for (int j = 0; j < 8; j++)
#pragma unroll
            for (int qi = 0; qi < 4; qi++) s[j][qi] = 0.f;

#pragma unroll
        for (int ks = 0; ks < 4; ks++) {
#pragma unroll
            for (int jp = 0; jp < 4; jp++) {
                uint32_t off = ((jp * 16 + browB) * 36 + ks * 8 + bkB) * 4;
                uint32_t k0, k1, k2, k3;
                ldmatrix_x4(k0, k1, k2, k3, aKh + off);
                int j = 2 * jp;
                mma16816(s[j],   qh[ks][0], qh[ks][1], qh[ks][2], qh[ks][3], k0, k1);
                mma16816(s[j],   ql[ks][0], ql[ks][1], ql[ks][2], ql[ks][3], k0, k1);
                mma16816(s[j+1], qh[ks][0], qh[ks][1], qh[ks][2], qh[ks][3], k2, k3);
                mma16816(s[j+1], ql[ks][0], ql[ks][1], ql[ks][2], ql[ks][3], k2, k3);
            }
        }

        // ---- online softmax (rows gid, gid+8; base-2 domain) ----
        float mb0 = -1e30f, mb1 = -1e30f;
#pragma unroll
        for (int j = 0; j < 8; j++) {
            mb0 = fmaxf(mb0, fmaxf(s[j][0], s[j][1]));
            mb1 = fmaxf(mb1, fmaxf(s[j][2], s[j][3]));
        }
        mb0 = fmaxf(mb0, __shfl_xor_sync(0xffffffffu, mb0, 1));
        mb0 = fmaxf(mb0, __shfl_xor_sync(0xffffffffu, mb0, 2));
        mb1 = fmaxf(mb1, __shfl_xor_sync(0xffffffffu, mb1, 1));
        mb1 = fmaxf(mb1, __shfl_xor_sync(0xffffffffu, mb1, 2));

        float mn0 = fmaxf(m0, mb0), mn1 = fmaxf(m1, mb1);
        float al0 = exp2f(m0 - mn0), al1 = exp2f(m1 - mn1);
        m0 = mn0; m1 = mn1;

        float rs0 = 0.f, rs1 = 0.f;
#pragma unroll
        for (int j = 0; j < 8; j++) {
            s[j][0] = exp2f(s[j][0] - mn0);
            s[j][1] = exp2f(s[j][1] - mn0);
            s[j][2] = exp2f(s[j][2] - mn1);
            s[j][3] = exp2f(s[j][3] - mn1);
            rs0 += s[j][0] + s[j][1];
            rs1 += s[j][2] + s[j][3];
        }
        rs0 += __shfl_xor_sync(0xffffffffu, rs0, 1);
        rs0 += __shfl_xor_sync(0xffffffffu, rs0, 2);
        rs1 += __shfl_xor_sync(0xffffffffu, rs1, 1);
        rs1 += __shfl_xor_sync(0xffffffffu, rs1, 2);
        l0 = l0 * al0 + rs0;
        l1 = l1 * al1 + rs1;

#pragma unroll
        for (int j = 0; j < 8; j++) {
            o[j][0] *= al0; o[j][1] *= al0;
            o[j][2] *= al1; o[j][3] *= al1;
        }

        // ---- O += P V (2-term: P*Vhi + P*Vlo) ----
#pragma unroll
        for (int jc = 0; jc < 4; jc++) {
            uint32_t ph[4];
            ph[0] = pack2h(s[2*jc][0],   s[2*jc][1]);
            ph[1] = pack2h(s[2*jc][2],   s[2*jc][3]);
            ph[2] = pack2h(s[2*jc+1][0], s[2*jc+1][1]);
            ph[3] = pack2h(s[2*jc+1][2], s[2*jc+1][3]);
#pragma unroll
            for (int fp = 0; fp < 4; fp++) {
                uint32_t off = ((fp * 16 + browB) * 36 + jc * 8 + bkB) * 4;
                uint32_t h0, h1, h2, h3, c0, c1, c2, c3;
                ldmatrix_x4(h0, h1, h2, h3, aVh + off);
                ldmatrix_x4(c0, c1, c2, c3, aVl + off);
                int jf = 2 * fp;
                mma16816(o[jf],   ph[0], ph[1], ph[2], ph[3], h0, h1);
                mma16816(o[jf],   ph[0], ph[1], ph[2], ph[3], c0, c1);
                mma16816(o[jf+1], ph[0], ph[1], ph[2], ph[3], h2, h3);
                mma16816(o[jf+1], ph[0], ph[1], ph[2], ph[3], c2, c3);
            }
        }
        __syncthreads();
    }

    // ---- epilogue: write fp16-split attn directly ----
    float inv0 = 1.f / l0, inv1 = 1.f / l1;
    {
        uint32_t* ahi = (uint32_t*)g_ahi;
        uint32_t* alo = (uint32_t*)g_alo;
        int r0 = nt * 128 + wid * 16 + gid;
        size_t base0 = (((size_t)b * CN + r0) * CC + h * CD) / 2;
        size_t base1 = base0 + 4 * CC;
#pragma unroll
        for (int jf = 0; jf < 8; jf++) {
            int colw = (jf * 8 + 2 * tig) / 2;
            uint32_t h0, l0w, h1, l1w;
            split2h(o[jf][0] * inv0, o[jf][1] * inv0, h0, l0w);
            split2h(o[jf][2] * inv1, o[jf][3] * inv1, h1, l1w);
            ahi[base0 + colw] = h0;  alo[base0 + colw] = l0w;
            ahi[base1 + colw] = h1;  alo[base1 + colw] = l1w;
        }
    }
}

// ----------------------------------------------------------------------------
// Launch
// ----------------------------------------------------------------------------
extern "C" void kernel_launch(void* const* d_in, const int* in_sizes, int n_in,
                              void* d_out, int out_size)
{
    const float* x     = (const float*)d_in[0];
    const float* ctx   = (const float*)d_in[1];
    const float* fc    = (const float*)d_in[2];
    const float* Wq    = (const float*)d_in[3];
    const float* Wkv   = (const float*)d_in[4];
    const float* Wproj = (const float*)d_in[5];
    const float* bproj = (const float*)d_in[6];
    float* out = (float*)d_out;

    float *q, *kvp;
    uint4 *ahi, *alo, *wh;
    cudaGetSymbolAddress((void**)&q,    g_q);
    cudaGetSymbolAddress((void**)&kvp,  g_kv);
    cudaGetSymbolAddress((void**)&ahi,  g_ahi);
    cudaGetSymbolAddress((void**)&alo,  g_alo);
    cudaGetSymbolAddress((void**)&wh,   g_wh);

    const __half* ah = (const __half*)ahi;
    const __half* al = (const __half*)alo;
    const __half* wp = (const __half*)wh;

    cudaFuncSetAttribute(flash_mma_kernel,
                         cudaFuncAttributeMaxDynamicSharedMemorySize, FLASH_SMEM);
    cudaFuncSetAttribute(gemm_fp16_kernel,
                         cudaFuncAttributeMaxDynamicSharedMemorySize, GEMM_SMEM);

    const int actN8 = CB * CN * CC / 8;
    const int wN8   = CC * CC / 8;

    // 1) q = x @ Wq^T
    split_kernel<<<(actN8 + 255) / 256, 256>>>(x, ahi, alo, actN8);
    cvt_kernel<<<(wN8 + 255) / 256, 256>>>(Wq, wh, wN8);
    gemm_fp16_kernel<<<dim3(CC / 128, (CB * CN) / 128), 128, GEMM_SMEM>>>(
        ah, al, wp, q, CB * CN, CC, CC, nullptr);

    // 2) kv = context @ Wkv^T
    split_kernel<<<(actN8 + 255) / 256, 256>>>(ctx, ahi, alo, actN8);
    cvt_kernel<<<(2 * wN8 + 255) / 256, 256>>>(Wkv, wh, 2 * wN8);
    gemm_fp16_kernel<<<dim3((2 * CC) / 128, (CB * CM) / 128), 128, GEMM_SMEM>>>(
        ah, al, wp, kvp, CB * CM, 2 * CC, CC, nullptr);

    // 3) convert pre-pass: k rope+cvt, v split+transpose
    conv_kernel<<<dim3(CM / 64, CH, CB), 256>>>(fc);

    // 4) flash attention (Q-rope fused; writes fp16-split attn)
    flash_mma_kernel<<<dim3(CN / 128, CH, CB), 256, FLASH_SMEM>>>(q, fc);

    // 5) out = attn @ Wproj^T + bproj
    cvt_kernel<<<(wN8 + 255) / 256, 256>>>(Wproj, wh, wN8);
    gemm_fp16_kernel<<<dim3(CC / 128, (CB * CN) / 128), 128, GEMM_SMEM>>>(
        ah, al, wp, out, CB * CN, CC, CC, bproj);
}

// round 15
// speedup vs baseline: 1.0943x; 1.0943x over previous
#include <cuda_runtime.h>
#include <cuda_fp16.h>
#include <cstdint>

// Problem constants
constexpr int CB = 4;      // batch
constexpr int CN = 2048;   // query seq
constexpr int CM = 2048;   // context seq
constexpr int CC = 1024;   // channels
constexpr int CH = 16;     // heads
constexpr int CD = 64;     // head dim

// Scratch (device globals: allocation-free rule)
__device__ float g_q[(size_t)CB * CN * CC];          // 32 MB
__device__ float g_kv[(size_t)CB * CM * 2 * CC];     // 64 MB

// fp16 K (single, rope'd) and V (2-term split, transposed [b][h][d][m])
constexpr size_t KV_U4 = (size_t)CB * CH * CM * CD / 8;
__device__ uint4 g_kh[KV_U4];
__device__ uint4 g_vhi[KV_U4];
__device__ uint4 g_vlo[KV_U4];

// fp16-split activation operand (x -> ctx -> attn): hi+lo
constexpr size_t ACT_U4 = (size_t)CB * CN * CC / 8;
__device__ uint4 g_ahi[ACT_U4];
__device__ uint4 g_alo[ACT_U4];
// fp16 single weight operand (Wq -> Wkv -> Wproj)
constexpr size_t W_U4 = (size_t)2 * CC * CC / 8;
__device__ uint4 g_wh[W_U4];

// ============================================================================
// mma.sync m16n8k16 f16 -> f32, ldmatrix
// ============================================================================
__device__ __forceinline__ void mma16816(float* d,
    uint32_t a0, uint32_t a1, uint32_t a2, uint32_t a3,
    uint32_t b0, uint32_t b1)
{
    asm volatile(
        "mma.sync.aligned.m16n8k16.row.col.f32.f16.f16.f32 "
        "{%0,%1,%2,%3}, {%4,%5,%6,%7}, {%8,%9}, {%0,%1,%2,%3};"
        : "+f"(d[0]), "+f"(d[1]), "+f"(d[2]), "+f"(d[3])
        : "r"(a0), "r"(a1), "r"(a2), "r"(a3), "r"(b0), "r"(b1));
}

__device__ __forceinline__ void ldmatrix_x4(
    uint32_t& r0, uint32_t& r1, uint32_t& r2, uint32_t& r3, uint32_t addr)
{
    asm volatile(
        "ldmatrix.sync.aligned.m8n8.x4.shared.b16 {%0,%1,%2,%3}, [%4];"
        : "=r"(r0), "=r"(r1), "=r"(r2), "=r"(r3) : "r"(addr));
}

__device__ __forceinline__ uint32_t pack2h(float x, float y) {
    __half2 t = __floats2half2_rn(x, y);
    return *(uint32_t*)&t;
}
__device__ __forceinline__ void split2h(float x, float y, uint32_t& h, uint32_t& l) {
    __half hx = __float2half_rn(x);
    __half hy = __float2half_rn(y);
    float rx = x - __half2float(hx);
    float ry = y - __half2float(hy);
    __half2 th = __halves2half2(hx, hy);
    __half2 tl = __halves2half2(__float2half_rn(rx), __float2half_rn(ry));
    h = *(uint32_t*)&th;
    l = *(uint32_t*)&tl;
}

// 8 floats -> packed hi/lo fp16 (uint4 each)
__device__ __forceinline__ void cvt8_split(const float* g, uint4& hi, uint4& lo) {
    float4 a = *(const float4*)g;
    float4 b = *(const float4*)(g + 4);
    uint32_t* ph = (uint32_t*)&hi;
    uint32_t* pl = (uint32_t*)&lo;
    split2h(a.x, a.y, ph[0], pl[0]);
    split2h(a.z, a.w, ph[1], pl[1]);
    split2h(b.x, b.y, ph[2], pl[2]);
    split2h(b.z, b.w, ph[3], pl[3]);
}
// 8 floats -> packed fp16 (uint4)
__device__ __forceinline__ uint4 cvt8h(const float* g) {
    float4 a = *(const float4*)g;
    float4 b = *(const float4*)(g + 4);
    uint4 r;
    r.x = pack2h(a.x, a.y); r.y = pack2h(a.z, a.w);
    r.z = pack2h(b.x, b.y); r.w = pack2h(b.z, b.w);
    return r;
}

__device__ __forceinline__ uint32_t smem_u32(const void* p) {
    uint32_t a;
    asm("{ .reg .u64 t; cvta.to.shared.u64 t, %1; cvt.u32.u64 %0, t; }"
        : "=r"(a) : "l"(p));
    return a;
}
__device__ __forceinline__ void cp_async16(uint32_t dst, const void* src) {
    asm volatile("cp.async.cg.shared.global [%0], [%1], 16;"
                 :: "r"(dst), "l"(src) : "memory");
}
__device__ __forceinline__ void cp_commit() {
    asm volatile("cp.async.commit_group;" ::: "memory");
}
__device__ __forceinline__ void cp_wait1() {
    asm volatile("cp.async.wait_group 1;" ::: "memory");
}

// ============================================================================
// split_kernel: fp32[n] -> fp16 hi[n], lo[n].   cvt_kernel: fp32 -> fp16.
// ============================================================================
__global__ void __launch_bounds__(256) split_kernel(
    const float* __restrict__ src, uint4* __restrict__ hi,
    uint4* __restrict__ lo, int n8)
{
    int i = blockIdx.x * blockDim.x + threadIdx.x;
    if (i >= n8) return;
    uint4 h, l;
    cvt8_split(src + (size_t)i * 8, h, l);
    hi[i] = h;
    lo[i] = l;
}

__global__ void __launch_bounds__(256) cvt_kernel(
    const float* __restrict__ src, uint4* __restrict__ dst, int n8)
{
    int i = blockIdx.x * blockDim.x + threadIdx.x;
    if (i >= n8) return;
    dst[i] = cvt8h(src + (size_t)i * 8);
}

// ============================================================================
// NT GEMM: C[M,N] = A[M,K] * B[N,K]^T (+bias). A = fp16 hi+lo, B = fp16.
// 2-term emulation. CTA 128x128, 8 warps (4m x 2n, warp 32x64) — R12 shape.
// BK=64 (stride-36 rows, flash-proven layout), double-buffered cp.async.
// ============================================================================
constexpr int GS2 = 36;                  // words per smem row (32 data + 4 pad)
constexpr int GT2 = 128 * GS2;           // words per tile (4608)
constexpr int GBUF = 3 * GT2;            // Ahi, Alo, B (13824 words)
constexpr int GEMM_SMEM = 2 * GBUF * 4;  // 110592 bytes

__global__ void __launch_bounds__(256) gemm_fp16_kernel(
    const __half* __restrict__ Ahi, const __half* __restrict__ Alo,
    const __half* __restrict__ Bh,
    float* __restrict__ C, int M, int N, int K, const float* __restrict__ bias)
{
    extern __shared__ uint32_t gsm[];
    const uint32_t smb = smem_u32(gsm);

    const int tid = threadIdx.x;
    const int wid = tid >> 5;
    const int lane = tid & 31;
    const int warp_m = wid & 3;
    const int warp_n = wid >> 2;
    const int m0 = blockIdx.y * 128;
    const int n0 = blockIdx.x * 128;

    const int lrow16 = lane & 15;
    const int lhiA   = (lane >> 4) * 4;
    const int browB  = ((lane >> 4) & 1) * 8 + (lane & 7);
    const int bkB    = ((lane >> 3) & 1) * 4;

    float acc[2][8][4];
#pragma unroll
    for (int i = 0; i < 2; i++)
#pragma unroll
        for (int j = 0; j < 8; j++)
#pragma unroll
            for (int q = 0; q < 4; q++) acc[i][j][q] = 0.f;

    // loader: 128 rows x 8 chunks (16B) per tile; 2 threads/row x 4 chunks.
    const int lrow = tid >> 1;
    auto issue = [&](int kc, int buf) {
        const int k0 = kc * 64;
        const uint32_t base = smb + buf * GBUF * 4;
#pragma unroll
        for (int c = 0; c < 4; c++) {
            int chunk = (tid & 1) * 4 + c;   // 0..7
            uint32_t so = base + (lrow * GS2 + chunk * 4) * 4;
            size_t aof = ((size_t)(m0 + lrow) * K + k0 + chunk * 8) * 2;
            size_t bof = ((size_t)(n0 + lrow) * K + k0 + chunk * 8) * 2;
            cp_async16(so,               (const char*)Ahi + aof);
            cp_async16(so + GT2 * 4,     (const char*)Alo + aof);
            cp_async16(so + 2 * GT2 * 4, (const char*)Bh + bof);
        }
    };

    const int niter = K / 64;
    issue(0, 0);
    cp_commit();

    for (int kc = 0; kc < niter; kc++) {
        int buf = kc & 1;
        if (kc + 1 < niter) issue(kc + 1, buf ^ 1);
        cp_commit();
        cp_wait1();
        __syncthreads();

        const uint32_t aAhi = smb + buf * GBUF * 4;
        const uint32_t aAlo = aAhi + GT2 * 4;
        const uint32_t aB   = aAhi + 2 * GT2 * 4;

#pragma unroll
        for (int ks = 0; ks < 4; ks++) {
            uint32_t ah[2][4], al[2][4];
#pragma unroll
            for (int i = 0; i < 2; i++) {
                uint32_t off = ((warp_m * 32 + i * 16 + lrow16) * GS2 + ks * 8 + lhiA) * 4;
                ldmatrix_x4(ah[i][0], ah[i][1], ah[i][2], ah[i][3], aAhi + off);
                ldmatrix_x4(al[i][0], al[i][1], al[i][2], al[i][3], aAlo + off);
            }
#pragma unroll
            for (int jp = 0; jp < 4; jp++) {
                uint32_t b0, b1, b2, b3;
                uint32_t bd = aB + ((warp_n * 64 + jp * 16 + browB) * GS2 + ks * 8 + bkB) * 4;
                ldmatrix_x4(b0, b1, b2, b3, bd);
#pragma unroll
                for (int i = 0; i < 2; i++) {
                    mma16816(acc[i][2*jp],   ah[i][0], ah[i][1], ah[i][2], ah[i][3], b0, b1);
                    mma16816(acc[i][2*jp],   al[i][0], al[i][1], al[i][2], al[i][3], b0, b1);
                    mma16816(acc[i][2*jp+1], ah[i][0], ah[i][1], ah[i][2], ah[i][3], b2, b3);
                    mma16816(acc[i][2*jp+1], al[i][0], al[i][1], al[i][2], al[i][3], b2, b3);
                }
            }
        }
        __syncthreads();
    }

#pragma unroll
    for (int i = 0; i < 2; i++) {
        int row = m0 + warp_m * 32 + i * 16 + (lane >> 2);
#pragma unroll
        for (int j = 0; j < 8; j++) {
            int col = n0 + warp_n * 64 + j * 8 + (lane & 3) * 2;
            float2 w0, w1;
            w0.x = acc[i][j][0]; w0.y = acc[i][j][1];
            w1.x = acc[i][j][2]; w1.y = acc[i][j][3];
            if (bias) {
                float2 bb = *(const float2*)(bias + col);
                w0.x += bb.x; w0.y += bb.y;
                w1.x += bb.x; w1.y += bb.y;
            }
            *(float2*)(C + (size_t)row * N + col) = w0;
            *(float2*)(C + (size_t)(row + 8) * N + col) = w1;
        }
    }
}

// ----------------------------------------------------------------------------
// Convert pre-pass: K-RoPE + fp16 cvt (single); V fp16 split + transpose.
// ----------------------------------------------------------------------------
__global__ void __launch_bounds__(256) conv_kernel(const float* __restrict__ fc)
{
    __shared__ float sv[64][68];
    const int tid = threadIdx.x;
    const int blk = blockIdx.x, h = blockIdx.y, b = blockIdx.z;
    const int bh = b * CH + h;

    const int kl = tid >> 2;
    const int ch = tid & 3;
    const int m  = blk * 64 + kl;
    const int d0 = ch * 16;

    // ---- K: read, rope, cvt fp16, store [b][h][m][d] ----
    {
        const float* kp = g_kv + ((size_t)b * CM + m) * (2 * CC) + h * CD + d0;
        float v[16];
        *(float4*)(v + 0)  = *(const float4*)(kp + 0);
        *(float4*)(v + 4)  = *(const float4*)(kp + 4);
        *(float4*)(v + 8)  = *(const float4*)(kp + 8);
        *(float4*)(v + 12) = *(const float4*)(kp + 12);
        uint4 kk[2];
        uint32_t* pk = (uint32_t*)kk;
#pragma unroll
        for (int i = 0; i < 8; i++) {
            int d2 = ch * 8 + i;
            float2 f = *(const float2*)(fc + m * 64 + d2 * 2);
            float rx = v[2*i] * f.x - v[2*i+1] * f.y;
            float ry = v[2*i+1] * f.x + v[2*i] * f.y;
            pk[i] = pack2h(rx, ry);
        }
        size_t o = (((size_t)bh * CM + m) * CD + d0) / 8;
        g_kh[o] = kk[0]; g_kh[o + 1] = kk[1];
    }

    // ---- V: stage to smem, transpose, split fp16, store [b][h][d][m] ----
    {
        const float* vp = g_kv + ((size_t)b * CM + m) * (2 * CC) + CC + h * CD + d0;
        float4 a = *(const float4*)(vp + 0);
        float4 c = *(const float4*)(vp + 4);
        float4 e = *(const float4*)(vp + 8);
        float4 g = *(const float4*)(vp + 12);
        *(float4*)&sv[kl][d0 + 0]  = a;
        *(float4*)&sv[kl][d0 + 4]  = c;
        *(float4*)&sv[kl][d0 + 8]  = e;
        *(float4*)&sv[kl][d0 + 12] = g;
    }
    __syncthreads();
    {
        const int d  = tid >> 2;
        const int kc = tid & 3;
        uint4 hi[2], lo[2];
        uint32_t* ph = (uint32_t*)hi;
        uint32_t* pl = (uint32_t*)lo;
#pragma unroll
        for (int i = 0; i < 8; i++) {
            int key = kc * 16 + 2 * i;
            split2h(sv[key][d], sv[key + 1][d], ph[i], pl[i]);
        }
        size_t o = (((size_t)bh * CD + d) * CM + blk * 64 + kc * 16) / 8;
        g_vhi[o] = hi[0]; g_vhi[o + 1] = hi[1];
        g_vlo[o] = lo[0]; g_vlo[o + 1] = lo[1];
    }
}

// ----------------------------------------------------------------------------
// Tensor-core flash attention, fp16 2-term (Q split, K single; P single,
// V split). Q-RoPE fused. Epilogue writes fp16-split attn into g_ahi/g_alo.
// ----------------------------------------------------------------------------
constexpr int FT = 64 * 36;
constexpr int FBUF = 3 * FT;              // Kh, Vhi, Vlo
constexpr int FLASH_SMEM = 2 * FBUF * 4;  // 55296 bytes

__global__ void __launch_bounds__(256) flash_mma_kernel(
    const float* __restrict__ q, const float* __restrict__ fc)
{
    extern __shared__ uint32_t fsm[];
    const int tid  = threadIdx.x;
    const int wid  = tid >> 5;
    const int lane = tid & 31;
    const int gid  = lane >> 2;
    const int tig  = lane & 3;
    const int nt = blockIdx.x, h = blockIdx.y, b = blockIdx.z;
    const int bh = b * CH + h;

    const uint32_t smb = smem_u32(fsm);

    const int browB = ((lane >> 4) & 1) * 8 + (lane & 7);
    const int bkB   = ((lane >> 3) & 1) * 4;

    const int lrow8 = tid >> 3;
    const int lc8   = tid & 7;
    auto issue = [&](int jt, int buf) {
#pragma unroll
        for (int half = 0; half < 2; half++) {
            int row = lrow8 + half * 32;
            uint32_t so = smb + buf * (FBUF * 4) + (row * 36 + lc8 * 4) * 4;
            size_t kof = (((size_t)bh * CM + jt * 64 + row) * CD + lc8 * 8) * 2;
            size_t vof = (((size_t)bh * CD + row) * CM + jt * 64 + lc8 * 8) * 2;
            cp_async16(so,               (const char*)g_kh + kof);
            cp_async16(so + FT * 4,     (const char*)g_vhi + vof);
            cp_async16(so + 2 * FT * 4, (const char*)g_vlo + vof);
        }
    };

    issue(0, 0);
    cp_commit();

    // ---- Q fragments: rope + scale + fp16 split ----
    const float SCALE = 0.125f * 1.44269504088896340736f;
    uint32_t qh[4][4], ql[4][4];
    {
        const int n0_ = nt * 128 + wid * 16 + gid;
        const float* qr0 = q + ((size_t)b * CN + n0_) * CC + h * CD;
        const float* qr1 = qr0 + 8 * CC;
        const float* fc0 = fc + n0_ * 64;
        const float* fc1 = fc0 + 8 * 64;
#pragma unroll
        for (int ks = 0; ks < 4; ks++) {
            int c = ks * 16 + 2 * tig;
            int d2 = c >> 1;
            float2 f0a = *(const float2*)(fc0 + d2 * 2);
            float2 f0b = *(const float2*)(fc0 + (d2 + 4) * 2);
            float2 f1a = *(const float2*)(fc1 + d2 * 2);
            float2 f1b = *(const float2*)(fc1 + (d2 + 4) * 2);
            float2 x00 = *(const float2*)(qr0 + c);
            float2 x10 = *(const float2*)(qr1 + c);
            float2 x01 = *(const float2*)(qr0 + c + 8);
            float2 x11 = *(const float2*)(qr1 + c + 8);
            float r00x = x00.x * f0a.x - x00.y * f0a.y;
            float r00y = x00.y * f0a.x + x00.x * f0a.y;
            float r10x = x10.x * f1a.x - x10.y * f1a.y;
            float r10y = x10.y * f1a.x + x10.x * f1a.y;
            float r01x = x01.x * f0b.x - x01.y * f0b.y;
            float r01y = x01.y * f0b.x + x01.x * f0b.y;
            float r11x = x11.x * f1b.x - x11.y * f1b.y;
            float r11y = x11.y * f1b.x + x11.x * f1b.y;
            split2h(r00x * SCALE, r00y * SCALE, qh[ks][0], ql[ks][0]);
            split2h(r10x * SCALE, r10y * SCALE, qh[ks][1], ql[ks][1]);
            split2h(r01x * SCALE, r01y * SCALE, qh[ks][2], ql[ks][2]);
            split2h(r11x * SCALE, r11y * SCALE, qh[ks][3], ql[ks][3]);
        }
    }

    float o[8][4];
#pragma unroll
    for (int j = 0; j < 8; j++)
#pragma unroll
        for (int qi = 0; qi < 4; qi++) o[j][qi] = 0.f;
    float m0 = -1e30f, m1 = -1e30f, l0 = 0.f, l1 = 0.f;

    const int nblocks = CM / 64;
    for (int jt = 0; jt < nblocks; jt++) {
        int buf = jt & 1;
        if (jt + 1 < nblocks) issue(jt + 1, buf ^ 1);
        cp_commit();
        cp_wait1();
        __syncthreads();

        const uint32_t aKh = smb + buf * FBUF * 4;
        const uint32_t aVh = aKh + FT * 4;
        const uint32_t aVl = aKh + 2 * FT * 4;

        // ---- S = Q K^T (2-term) ----
        float s[8][4];
#pragma unroll
        for (int j = 0; j < 8; j++)
#pragma unroll
            for (int qi = 0; qi < 4; qi++) s[j][qi] = 0.f;

#pragma unroll
        for (int ks = 0; ks < 4; ks++) {
#pragma unroll
            for (int jp = 0; jp < 4; jp++) {
                uint32_t off = ((jp * 16 + browB) * 36 + ks * 8 + bkB) * 4;
                uint32_t k0, k1, k2, k3;
                ldmatrix_x4(k0, k1, k2, k3, aKh + off);
                int j = 2 * jp;
                mma16816(s[j],   qh[ks][0], qh[ks][1], qh[ks][2], qh[ks][3], k0, k1);
                mma16816(s[j],   ql[ks][0], ql[ks][1], ql[ks][2], ql[ks][3], k0, k1);
                mma16816(s[j+1], qh[ks][0], qh[ks][1], qh[ks][2], qh[ks][3], k2, k3);
                mma16816(s[j+1], ql[ks][0], ql[ks][1], ql[ks][2], ql[ks][3], k2, k3);
            }
        }

        // ---- online softmax (rows gid, gid+8; base-2 domain) ----
        float mb0 = -1e30f, mb1 = -1e30f;
#pragma unroll
        for (int j = 0; j < 8; j++) {
            mb0 = fmaxf(mb0, fmaxf(s[j][0], s[j][1]));
            mb1 = fmaxf(mb1, fmaxf(s[j][2], s[j][3]));
        }
        mb0 = fmaxf(mb0, __shfl_xor_sync(0xffffffffu, mb0, 1));
        mb0 = fmaxf(mb0, __shfl_xor_sync(0xffffffffu, mb0, 2));
        mb1 = fmaxf(mb1, __shfl_xor_sync(0xffffffffu, mb1, 1));
        mb1 = fmaxf(mb1, __shfl_xor_sync(0xffffffffu, mb1, 2));

        float mn0 = fmaxf(m0, mb0), mn1 = fmaxf(m1, mb1);
        float al0 = exp2f(m0 - mn0), al1 = exp2f(m1 - mn1);
        m0 = mn0; m1 = mn1;

        float rs0 = 0.f, rs1 = 0.f;
#pragma unroll
        for (int j = 0; j < 8; j++) {
            s[j][0] = exp2f(s[j][0] - mn0);
            s[j][1] = exp2f(s[j][1] - mn0);
            s[j][2] = exp2f(s[j][2] - mn1);
            s[j][3] = exp2f(s[j][3] - mn1);
            rs0 += s[j][0] + s[j][1];
            rs1 += s[j][2] + s[j][3];
        }
        rs0 += __shfl_xor_sync(0xffffffffu, rs0, 1);
        rs0 += __shfl_xor_sync(0xffffffffu, rs0, 2);
        rs1 += __shfl_xor_sync(0xffffffffu, rs1, 1);
        rs1 += __shfl_xor_sync(0xffffffffu, rs1, 2);
        l0 = l0 * al0 + rs0;
        l1 = l1 * al1 + rs1;

#pragma unroll
        for (int j = 0; j < 8; j++) {
            o[j][0] *= al0; o[j][1] *= al0;
            o[j][2] *= al1; o[j][3] *= al1;
        }

        // ---- O += P V (2-term: P*Vhi + P*Vlo) ----
#pragma unroll
        for (int jc = 0; jc < 4; jc++) {
            uint32_t ph[4];
            ph[0] = pack2h(s[2*jc][0],   s[2*jc][1]);
            ph[1] = pack2h(s[2*jc][2],   s[2*jc][3]);
            ph[2] = pack2h(s[2*jc+1][0], s[2*jc+1][1]);
            ph[3] = pack2h(s[2*jc+1][2], s[2*jc+1][3]);
#pragma unroll
            for (int fp = 0; fp < 4; fp++) {
                uint32_t off = ((fp * 16 + browB) * 36 + jc * 8 + bkB) * 4;
                uint32_t h0, h1, h2, h3, c0, c1, c2, c3;
                ldmatrix_x4(h0, h1, h2, h3, aVh + off);
                ldmatrix_x4(c0, c1, c2, c3, aVl + off);
                int jf = 2 * fp;
                mma16816(o[jf],   ph[0], ph[1], ph[2], ph[3], h0, h1);
                mma16816(o[jf],   ph[0], ph[1], ph[2], ph[3], c0, c1);
                mma16816(o[jf+1], ph[0], ph[1], ph[2], ph[3], h2, h3);
                mma16816(o[jf+1], ph[0], ph[1], ph[2], ph[3], c2, c3);
            }
        }
        __syncthreads();
    }

    // ---- epilogue: write fp16-split attn directly ----
    float inv0 = 1.f / l0, inv1 = 1.f / l1;
    {
        uint32_t* ahi = (uint32_t*)g_ahi;
        uint32_t* alo = (uint32_t*)g_alo;
        int r0 = nt * 128 + wid * 16 + gid;
        size_t base0 = (((size_t)b * CN + r0) * CC + h * CD) / 2;
        size_t base1 = base0 + 4 * CC;
#pragma unroll
        for (int jf = 0; jf < 8; jf++) {
            int colw = (jf * 8 + 2 * tig) / 2;
            uint32_t h0, l0w, h1, l1w;
            split2h(o[jf][0] * inv0, o[jf][1] * inv0, h0, l0w);
            split2h(o[jf][2] * inv1, o[jf][3] * inv1, h1, l1w);
            ahi[base0 + colw] = h0;  alo[base0 + colw] = l0w;
            ahi[base1 + colw] = h1;  alo[base1 + colw] = l1w;
        }
    }
}

// ----------------------------------------------------------------------------
// Launch
// ----------------------------------------------------------------------------
extern "C" void kernel_launch(void* const* d_in, const int* in_sizes, int n_in,
                              void* d_out, int out_size)
{
    const float* x     = (const float*)d_in[0];
    const float* ctx   = (const float*)d_in[1];
    const float* fc    = (const float*)d_in[2];
    const float* Wq    = (const float*)d_in[3];
    const float* Wkv   = (const float*)d_in[4];
    const float* Wproj = (const float*)d_in[5];
    const float* bproj = (const float*)d_in[6];
    float* out = (float*)d_out;

    float *q, *kvp;
    uint4 *ahi, *alo, *wh;
    cudaGetSymbolAddress((void**)&q,    g_q);
    cudaGetSymbolAddress((void**)&kvp,  g_kv);
    cudaGetSymbolAddress((void**)&ahi,  g_ahi);
    cudaGetSymbolAddress((void**)&alo,  g_alo);
    cudaGetSymbolAddress((void**)&wh,   g_wh);

    const __half* ah = (const __half*)ahi;
    const __half* al = (const __half*)alo;
    const __half* wp = (const __half*)wh;

    cudaFuncSetAttribute(flash_mma_kernel,
                         cudaFuncAttributeMaxDynamicSharedMemorySize, FLASH_SMEM);
    cudaFuncSetAttribute(gemm_fp16_kernel,
                         cudaFuncAttributeMaxDynamicSharedMemorySize, GEMM_SMEM);

    const int actN8 = CB * CN * CC / 8;
    const int wN8   = CC * CC / 8;

    // 1) q = x @ Wq^T
    split_kernel<<<(actN8 + 255) / 256, 256>>>(x, ahi, alo, actN8);
    cvt_kernel<<<(wN8 + 255) / 256, 256>>>(Wq, wh, wN8);
    gemm_fp16_kernel<<<dim3(CC / 128, (CB * CN) / 128), 256, GEMM_SMEM>>>(
        ah, al, wp, q, CB * CN, CC, CC, nullptr);

    // 2) kv = context @ Wkv^T
    split_kernel<<<(actN8 + 255) / 256, 256>>>(ctx, ahi, alo, actN8);
    cvt_kernel<<<(2 * wN8 + 255) / 256, 256>>>(Wkv, wh, 2 * wN8);
    gemm_fp16_kernel<<<dim3((2 * CC) / 128, (CB * CM) / 128), 256, GEMM_SMEM>>>(
        ah, al, wp, kvp, CB * CM, 2 * CC, CC, nullptr);

    // 3) convert pre-pass: k rope+cvt, v split+transpose
    conv_kernel<<<dim3(CM / 64, CH, CB), 256>>>(fc);

    // 4) flash attention (Q-rope fused; writes fp16-split attn)
    flash_mma_kernel<<<dim3(CN / 128, CH, CB), 256, FLASH_SMEM>>>(q, fc);

    // 5) out = attn @ Wproj^T + bproj
    cvt_kernel<<<(wN8 + 255) / 256, 256>>>(Wproj, wh, wN8);
    gemm_fp16_kernel<<<dim3(CC / 128, (CB * CN) / 128), 256, GEMM_SMEM>>>(
        ah, al, wp, out, CB * CN, CC, CC, bproj);
}

// round 16
// speedup vs baseline: 1.1185x; 1.0221x over previous
#include <cuda_runtime.h>
#include <cuda_fp16.h>
#include <cstdint>

// Problem constants
constexpr int CB = 4;      // batch
constexpr int CN = 2048;   // query seq
constexpr int CM = 2048;   // context seq
constexpr int CC = 1024;   // channels
constexpr int CH = 16;     // heads
constexpr int CD = 64;     // head dim

// Scratch (device globals: allocation-free rule)
__device__ float g_q[(size_t)CB * CN * CC];          // 32 MB
__device__ float g_kv[(size_t)CB * CM * 2 * CC];     // 64 MB (V half used)

// fp16 K (single, rope'd) and V (2-term split, transposed [b][h][d][m])
constexpr size_t KV_U4 = (size_t)CB * CH * CM * CD / 8;
__device__ uint4 g_kh[KV_U4];
__device__ uint4 g_vhi[KV_U4];
__device__ uint4 g_vlo[KV_U4];

// fp16-split activation operand (x -> ctx -> attn): hi+lo
constexpr size_t ACT_U4 = (size_t)CB * CN * CC / 8;
__device__ uint4 g_ahi[ACT_U4];
__device__ uint4 g_alo[ACT_U4];
// fp16 single weight operand (Wq -> Wkv -> Wproj)
constexpr size_t W_U4 = (size_t)2 * CC * CC / 8;
__device__ uint4 g_wh[W_U4];

// ============================================================================
// mma.sync m16n8k16 f16 -> f32, ldmatrix
// ============================================================================
__device__ __forceinline__ void mma16816(float* d,
    uint32_t a0, uint32_t a1, uint32_t a2, uint32_t a3,
    uint32_t b0, uint32_t b1)
{
    asm volatile(
        "mma.sync.aligned.m16n8k16.row.col.f32.f16.f16.f32 "
        "{%0,%1,%2,%3}, {%4,%5,%6,%7}, {%8,%9}, {%0,%1,%2,%3};"
        : "+f"(d[0]), "+f"(d[1]), "+f"(d[2]), "+f"(d[3])
        : "r"(a0), "r"(a1), "r"(a2), "r"(a3), "r"(b0), "r"(b1));
}

__device__ __forceinline__ void ldmatrix_x4(
    uint32_t& r0, uint32_t& r1, uint32_t& r2, uint32_t& r3, uint32_t addr)
{
    asm volatile(
        "ldmatrix.sync.aligned.m8n8.x4.shared.b16 {%0,%1,%2,%3}, [%4];"
        : "=r"(r0), "=r"(r1), "=r"(r2), "=r"(r3) : "r"(addr));
}

__device__ __forceinline__ uint32_t pack2h(float x, float y) {
    __half2 t = __floats2half2_rn(x, y);
    return *(uint32_t*)&t;
}
__device__ __forceinline__ void split2h(float x, float y, uint32_t& h, uint32_t& l) {
    __half hx = __float2half_rn(x);
    __half hy = __float2half_rn(y);
    float rx = x - __half2float(hx);
    float ry = y - __half2float(hy);
    __half2 th = __halves2half2(hx, hy);
    __half2 tl = __halves2half2(__float2half_rn(rx), __float2half_rn(ry));
    h = *(uint32_t*)&th;
    l = *(uint32_t*)&tl;
}

// 8 floats -> packed hi/lo fp16 (uint4 each)
__device__ __forceinline__ void cvt8_split(const float* g, uint4& hi, uint4& lo) {
    float4 a = *(const float4*)g;
    float4 b = *(const float4*)(g + 4);
    uint32_t* ph = (uint32_t*)&hi;
    uint32_t* pl = (uint32_t*)&lo;
    split2h(a.x, a.y, ph[0], pl[0]);
    split2h(a.z, a.w, ph[1], pl[1]);
    split2h(b.x, b.y, ph[2], pl[2]);
    split2h(b.z, b.w, ph[3], pl[3]);
}
// 8 floats -> packed fp16 (uint4)
__device__ __forceinline__ uint4 cvt8h(const float* g) {
    float4 a = *(const float4*)g;
    float4 b = *(const float4*)(g + 4);
    uint4 r;
    r.x = pack2h(a.x, a.y); r.y = pack2h(a.z, a.w);
    r.z = pack2h(b.x, b.y); r.w = pack2h(b.z, b.w);
    return r;
}

__device__ __forceinline__ uint32_t smem_u32(const void* p) {
    uint32_t a;
    asm("{ .reg .u64 t; cvta.to.shared.u64 t, %1; cvt.u32.u64 %0, t; }"
        : "=r"(a) : "l"(p));
    return a;
}
__device__ __forceinline__ void cp_async16(uint32_t dst, const void* src) {
    asm volatile("cp.async.cg.shared.global [%0], [%1], 16;"
                 :: "r"(dst), "l"(src) : "memory");
}
__device__ __forceinline__ void cp_commit() {
    asm volatile("cp.async.commit_group;" ::: "memory");
}
__device__ __forceinline__ void cp_wait1() {
    asm volatile("cp.async.wait_group 1;" ::: "memory");
}

// ============================================================================
// split_kernel: fp32[n] -> fp16 hi[n], lo[n].   cvt_kernel: fp32 -> fp16.
// ============================================================================
__global__ void __launch_bounds__(256) split_kernel(
    const float* __restrict__ src, uint4* __restrict__ hi,
    uint4* __restrict__ lo, int n8)
{
    int i = blockIdx.x * blockDim.x + threadIdx.x;
    if (i >= n8) return;
    uint4 h, l;
    cvt8_split(src + (size_t)i * 8, h, l);
    hi[i] = h;
    lo[i] = l;
}

__global__ void __launch_bounds__(256) cvt_kernel(
    const float* __restrict__ src, uint4* __restrict__ dst, int n8)
{
    int i = blockIdx.x * blockDim.x + threadIdx.x;
    if (i >= n8) return;
    dst[i] = cvt8h(src + (size_t)i * 8);
}

// ============================================================================
// GEMM mainloop (R12-proven): CTA 128x128, 8 warps (4m x 2n, warp 32x64),
// BK=32, double-buffered cp.async, 2-term (Ahi*B + Alo*B).
// Shared between the generic kernel and the kv-fused kernel via macro-free
// duplication (epilogues differ).
// ============================================================================
constexpr int GS = 20;                  // words per smem row (16 data + 4 pad)
constexpr int GT_TSZ = 128 * GS;        // words per tile (2560)
constexpr int GBUF = 3 * GT_TSZ;        // Ahi, Alo, B
constexpr int GEMM_SMEM = 2 * GBUF * 4; // 61440 bytes

#define GEMM_MAINLOOP(ACC)                                                      \
    const int lrow = tid >> 1;                                                  \
    auto issue = [&](int kc, int buf) {                                         \
        const int k0 = kc * 32;                                                 \
        const uint32_t base = smb + buf * GBUF * 4;                             \
        _Pragma("unroll")                                                       \
        for (int c = 0; c < 2; c++) {                                           \
            int chunk = (tid & 1) * 2 + c;                                      \
            uint32_t so = base + (lrow * GS + chunk * 4) * 4;                   \
            size_t aof = ((size_t)(m0 + lrow) * K + k0 + chunk * 8) * 2;        \
            size_t bof = ((size_t)(n0 + lrow) * K + k0 + chunk * 8) * 2;        \
            cp_async16(so,                  (const char*)Ahi + aof);            \
            cp_async16(so + GT_TSZ * 4,     (const char*)Alo + aof);            \
            cp_async16(so + 2 * GT_TSZ * 4, (const char*)Bh + bof);             \
        }                                                                       \
    };                                                                          \
    const int niter = K / 32;                                                   \
    issue(0, 0);                                                                \
    cp_commit();                                                                \
    for (int kc = 0; kc < niter; kc++) {                                        \
        int buf = kc & 1;                                                       \
        if (kc + 1 < niter) issue(kc + 1, buf ^ 1);                             \
        cp_commit();                                                            \
        cp_wait1();                                                             \
        __syncthreads();                                                        \
        const uint32_t aAhi = smb + buf * GBUF * 4;                             \
        const uint32_t aAlo = aAhi + GT_TSZ * 4;                                \
        const uint32_t aB   = aAhi + 2 * GT_TSZ * 4;                            \
        _Pragma("unroll")                                                       \
        for (int ks = 0; ks < 2; ks++) {                                        \
            uint32_t ah[2][4], al[2][4];                                        \
            _Pragma("unroll")                                                   \
            for (int i = 0; i < 2; i++) {                                       \
                uint32_t off = ((warp_m * 32 + i * 16 + lrow16) * GS            \
                                + ks * 8 + lhiA) * 4;                           \
                ldmatrix_x4(ah[i][0], ah[i][1], ah[i][2], ah[i][3], aAhi + off);\
                ldmatrix_x4(al[i][0], al[i][1], al[i][2], al[i][3], aAlo + off);\
            }                                                                   \
            _Pragma("unroll")                                                   \
            for (int jp = 0; jp < 4; jp++) {                                    \
                uint32_t b0, b1, b2, b3;                                        \
                uint32_t bd = aB + ((warp_n * 64 + jp * 16 + browB) * GS        \
                                    + ks * 8 + bkB) * 4;                        \
                ldmatrix_x4(b0, b1, b2, b3, bd);                                \
                _Pragma("unroll")                                               \
                for (int i = 0; i < 2; i++) {                                   \
                    mma16816(ACC[i][2*jp],   ah[i][0], ah[i][1], ah[i][2], ah[i][3], b0, b1); \
                    mma16816(ACC[i][2*jp],   al[i][0], al[i][1], al[i][2], al[i][3], b0, b1); \
                    mma16816(ACC[i][2*jp+1], ah[i][0], ah[i][1], ah[i][2], ah[i][3], b2, b3); \
                    mma16816(ACC[i][2*jp+1], al[i][0], al[i][1], al[i][2], al[i][3], b2, b3); \
                }                                                               \
            }                                                                   \
        }                                                                       \
        __syncthreads();                                                        \
    }

__global__ void __launch_bounds__(256) gemm_fp16_kernel(
    const __half* __restrict__ Ahi, const __half* __restrict__ Alo,
    const __half* __restrict__ Bh,
    float* __restrict__ C, int M, int N, int K, const float* __restrict__ bias)
{
    extern __shared__ uint32_t gsm[];
    const uint32_t smb = smem_u32(gsm);

    const int tid = threadIdx.x;
    const int wid = tid >> 5;
    const int lane = tid & 31;
    const int warp_m = wid & 3;
    const int warp_n = wid >> 2;
    const int m0 = blockIdx.y * 128;
    const int n0 = blockIdx.x * 128;

    const int lrow16 = lane & 15;
    const int lhiA   = (lane >> 4) * 4;
    const int browB  = ((lane >> 4) & 1) * 8 + (lane & 7);
    const int bkB    = ((lane >> 3) & 1) * 4;

    float acc[2][8][4];
#pragma unroll
    for (int i = 0; i < 2; i++)
#pragma unroll
        for (int j = 0; j < 8; j++)
#pragma unroll
            for (int q = 0; q < 4; q++) acc[i][j][q] = 0.f;

    GEMM_MAINLOOP(acc)

#pragma unroll
    for (int i = 0; i < 2; i++) {
        int row = m0 + warp_m * 32 + i * 16 + (lane >> 2);
#pragma unroll
        for (int j = 0; j < 8; j++) {
            int col = n0 + warp_n * 64 + j * 8 + (lane & 3) * 2;
            float2 w0, w1;
            w0.x = acc[i][j][0]; w0.y = acc[i][j][1];
            w1.x = acc[i][j][2]; w1.y = acc[i][j][3];
            if (bias) {
                float2 bb = *(const float2*)(bias + col);
                w0.x += bb.x; w0.y += bb.y;
                w1.x += bb.x; w1.y += bb.y;
            }
            *(float2*)(C + (size_t)row * N + col) = w0;
            *(float2*)(C + (size_t)(row + 8) * N + col) = w1;
        }
    }
}

// ============================================================================
// KV GEMM with fused K epilogue: N = 2048 (cols <1024 = K, >=1024 = V).
// K-region CTAs: apply RoPE + fp16 cvt, write g_kh ([b][h][m][d] as words).
// V-region CTAs: write fp32 into g_kv (same layout as before).
// ============================================================================
__global__ void __launch_bounds__(256) gemm_kv_kernel(
    const __half* __restrict__ Ahi, const __half* __restrict__ Alo,
    const __half* __restrict__ Bh,
    float* __restrict__ C, int M, int N, int K,
    const float* __restrict__ fc)
{
    extern __shared__ uint32_t gsm[];
    const uint32_t smb = smem_u32(gsm);

    const int tid = threadIdx.x;
    const int wid = tid >> 5;
    const int lane = tid & 31;
    const int warp_m = wid & 3;
    const int warp_n = wid >> 2;
    const int m0 = blockIdx.y * 128;
    const int n0 = blockIdx.x * 128;

    const int lrow16 = lane & 15;
    const int lhiA   = (lane >> 4) * 4;
    const int browB  = ((lane >> 4) & 1) * 8 + (lane & 7);
    const int bkB    = ((lane >> 3) & 1) * 4;

    float acc[2][8][4];
#pragma unroll
    for (int i = 0; i < 2; i++)
#pragma unroll
        for (int j = 0; j < 8; j++)
#pragma unroll
            for (int q = 0; q < 4; q++) acc[i][j][q] = 0.f;

    GEMM_MAINLOOP(acc)

    if (n0 < CC) {
        // ---- K region: rope + fp16, write g_kh directly ----
        uint32_t* khw = (uint32_t*)g_kh;
#pragma unroll
        for (int i = 0; i < 2; i++) {
            int row = m0 + warp_m * 32 + i * 16 + (lane >> 2);
            int b    = row >> 11;          // /2048
            int mtok = row & 2047;
#pragma unroll
            for (int j = 0; j < 8; j++) {
                int col = n0 + warp_n * 64 + j * 8 + (lane & 3) * 2;
                int h = col >> 6;
                int d = col & 63;          // even
                float2 f0 = *(const float2*)(fc + mtok * 64 + d);
                float2 f1 = *(const float2*)(fc + (mtok + 8) * 64 + d);
                float r0x = acc[i][j][0] * f0.x - acc[i][j][1] * f0.y;
                float r0y = acc[i][j][1] * f0.x + acc[i][j][0] * f0.y;
                float r1x = acc[i][j][2] * f1.x - acc[i][j][3] * f1.y;
                float r1y = acc[i][j][3] * f1.x + acc[i][j][2] * f1.y;
                size_t idx0 = (((size_t)(b * CH + h) * CM + mtok) * CD + d) >> 1;
                khw[idx0]            = pack2h(r0x, r0y);
                khw[idx0 + 8 * 32]   = pack2h(r1x, r1y);   // +8 rows * 32 words
            }
        }
    } else {
        // ---- V region: fp32 to g_kv (unchanged layout) ----
#pragma unroll
        for (int i = 0; i < 2; i++) {
            int row = m0 + warp_m * 32 + i * 16 + (lane >> 2);
#pragma unroll
            for (int j = 0; j < 8; j++) {
                int col = n0 + warp_n * 64 + j * 8 + (lane & 3) * 2;
                float2 w0, w1;
                w0.x = acc[i][j][0]; w0.y = acc[i][j][1];
                w1.x = acc[i][j][2]; w1.y = acc[i][j][3];
                *(float2*)(C + (size_t)row * N + col) = w0;
                *(float2*)(C + (size_t)(row + 8) * N + col) = w1;
            }
        }
    }
}

// ----------------------------------------------------------------------------
// Convert pre-pass (V only now): fp16 split + transpose to [b][h][d][m].
// ----------------------------------------------------------------------------
__global__ void __launch_bounds__(256) conv_v_kernel()
{
    __shared__ float sv[64][68];
    const int tid = threadIdx.x;
    const int blk = blockIdx.x, h = blockIdx.y, b = blockIdx.z;
    const int bh = b * CH + h;

    const int kl = tid >> 2;
    const int ch = tid & 3;
    const int m  = blk * 64 + kl;
    const int d0 = ch * 16;

    {
        const float* vp = g_kv + ((size_t)b * CM + m) * (2 * CC) + CC + h * CD + d0;
        float4 a = *(const float4*)(vp + 0);
        float4 c = *(const float4*)(vp + 4);
        float4 e = *(const float4*)(vp + 8);
        float4 g = *(const float4*)(vp + 12);
        *(float4*)&sv[kl][d0 + 0]  = a;
        *(float4*)&sv[kl][d0 + 4]  = c;
        *(float4*)&sv[kl][d0 + 8]  = e;
        *(float4*)&sv[kl][d0 + 12] = g;
    }
    __syncthreads();
    {
        const int d  = tid >> 2;
        const int kc = tid & 3;
        uint4 hi[2], lo[2];
        uint32_t* ph = (uint32_t*)hi;
        uint32_t* pl = (uint32_t*)lo;
#pragma unroll
        for (int i = 0; i < 8; i++) {
            int key = kc * 16 + 2 * i;
            split2h(sv[key][d], sv[key + 1][d], ph[i], pl[i]);
        }
        size_t o = (((size_t)bh * CD + d) * CM + blk * 64 + kc * 16) / 8;
        g_vhi[o] = hi[0]; g_vhi[o + 1] = hi[1];
        g_vlo[o] = lo[0]; g_vlo[o + 1] = lo[1];
    }
}

// ----------------------------------------------------------------------------
// Tensor-core flash attention, fp16 2-term (Q split, K single; P single,
// V split). Q-RoPE fused. Epilogue writes fp16-split attn into g_ahi/g_alo.
// (unchanged from R12)
// ----------------------------------------------------------------------------
constexpr int FT = 64 * 36;
constexpr int FBUF = 3 * FT;              // Kh, Vhi, Vlo
constexpr int FLASH_SMEM = 2 * FBUF * 4;  // 55296 bytes

__global__ void __launch_bounds__(256) flash_mma_kernel(
    const float* __restrict__ q, const float* __restrict__ fc)
{
    extern __shared__ uint32_t fsm[];
    const int tid  = threadIdx.x;
    const int wid  = tid >> 5;
    const int lane = tid & 31;
    const int gid  = lane >> 2;
    const int tig  = lane & 3;
    const int nt = blockIdx.x, h = blockIdx.y, b = blockIdx.z;
    const int bh = b * CH + h;

    const uint32_t smb = smem_u32(fsm);

    const int browB = ((lane >> 4) & 1) * 8 + (lane & 7);
    const int bkB   = ((lane >> 3) & 1) * 4;

    const int lrow8 = tid >> 3;
    const int lc8   = tid & 7;
    auto issue = [&](int jt, int buf) {
#pragma unroll
        for (int half = 0; half < 2; half++) {
            int row = lrow8 + half * 32;
            uint32_t so = smb + buf * (FBUF * 4) + (row * 36 + lc8 * 4) * 4;
            size_t kof = (((size_t)bh * CM + jt * 64 + row) * CD + lc8 * 8) * 2;
            size_t vof = (((size_t)bh * CD + row) * CM + jt * 64 + lc8 * 8) * 2;
            cp_async16(so,               (const char*)g_kh + kof);
            cp_async16(so + FT * 4,     (const char*)g_vhi + vof);
            cp_async16(so + 2 * FT * 4, (const char*)g_vlo + vof);
        }
    };

    issue(0, 0);
    cp_commit();

    // ---- Q fragments: rope + scale + fp16 split ----
    const float SCALE = 0.125f * 1.44269504088896340736f;
    uint32_t qh[4][4], ql[4][4];
    {
        const int n0_ = nt * 128 + wid * 16 + gid;
        const float* qr0 = q + ((size_t)b * CN + n0_) * CC + h * CD;
        const float* qr1 = qr0 + 8 * CC;
        const float* fc0 = fc + n0_ * 64;
        const float* fc1 = fc0 + 8 * 64;
#pragma unroll
        for (int ks = 0; ks < 4; ks++) {
            int c = ks * 16 + 2 * tig;
            int d2 = c >> 1;
            float2 f0a = *(const float2*)(fc0 + d2 * 2);
            float2 f0b = *(const float2*)(fc0 + (d2 + 4) * 2);
            float2 f1a = *(const float2*)(fc1 + d2 * 2);
            float2 f1b = *(const float2*)(fc1 + (d2 + 4) * 2);
            float2 x00 = *(const float2*)(qr0 + c);
            float2 x10 = *(const float2*)(qr1 + c);
            float2 x01 = *(const float2*)(qr0 + c + 8);
            float2 x11 = *(const float2*)(qr1 + c + 8);
            float r00x = x00.x * f0a.x - x00.y * f0a.y;
            float r00y = x00.y * f0a.x + x00.x * f0a.y;
            float r10x = x10.x * f1a.x - x10.y * f1a.y;
            float r10y = x10.y * f1a.x + x10.x * f1a.y;
            float r01x = x01.x * f0b.x - x01.y * f0b.y;
            float r01y = x01.y * f0b.x + x01.x * f0b.y;
            float r11x = x11.x * f1b.x - x11.y * f1b.y;
            float r11y = x11.y * f1b.x + x11.x * f1b.y;
            split2h(r00x * SCALE, r00y * SCALE, qh[ks][0], ql[ks][0]);
            split2h(r10x * SCALE, r10y * SCALE, qh[ks][1], ql[ks][1]);
            split2h(r01x * SCALE, r01y * SCALE, qh[ks][2], ql[ks][2]);
            split2h(r11x * SCALE, r11y * SCALE, qh[ks][3], ql[ks][3]);
        }
    }

    float o[8][4];
#pragma unroll
    for (int j = 0; j < 8; j++)
#pragma unroll
        for (int qi = 0; qi < 4; qi++) o[j][qi] = 0.f;
    float m0 = -1e30f, m1 = -1e30f, l0 = 0.f, l1 = 0.f;

    const int nblocks = CM / 64;
    for (int jt = 0; jt < nblocks; jt++) {
        int buf = jt & 1;
        if (jt + 1 < nblocks) issue(jt + 1, buf ^ 1);
        cp_commit();
        cp_wait1();
        __syncthreads();

        const uint32_t aKh = smb + buf * FBUF * 4;
        const uint32_t aVh = aKh + FT * 4;
        const uint32_t aVl = aKh + 2 * FT * 4;

        // ---- S = Q K^T (2-term) ----
        float s[8][4];
#pragma unroll
        for (int j = 0; j < 8; j++)
#pragma unroll
            for (int qi = 0; qi < 4; qi++) s[j][qi] = 0.f;

#pragma unroll
        for (int ks = 0; ks < 4; ks++) {
#pragma unroll
            for (int jp = 0; jp < 4; jp++) {
                uint32_t off = ((jp * 16 + browB) * 36 + ks * 8 + bkB) * 4;
                uint32_t k0, k1, k2, k3;
                ldmatrix_x4(k0, k1, k2, k3, aKh + off);
                int j = 2 * jp;
                mma16816(s[j],   qh[ks][0], qh[ks][1], qh[ks][2], qh[ks][3], k0, k1);
                mma16816(s[j],   ql[ks][0], ql[ks][1], ql[ks][2], ql[ks][3], k0, k1);
                mma16816(s[j+1], qh[ks][0], qh[ks][1], qh[ks][2], qh[ks][3], k2, k3);
                mma16816(s[j+1], ql[ks][0], ql[ks][1], ql[ks][2], ql[ks][3], k2, k3);
            }
        }

        // ---- online softmax (rows gid, gid+8; base-2 domain) ----
        float mb0 = -1e30f, mb1 = -1e30f;
#pragma unroll
        for (int j = 0; j < 8; j++) {
            mb0 = fmaxf(mb0, fmaxf(s[j][0], s[j][1]));
            mb1 = fmaxf(mb1, fmaxf(s[j][2], s[j][3]));
        }
        mb0 = fmaxf(mb0, __shfl_xor_sync(0xffffffffu, mb0, 1));
        mb0 = fmaxf(mb0, __shfl_xor_sync(0xffffffffu, mb0, 2));
        mb1 = fmaxf(mb1, __shfl_xor_sync(0xffffffffu, mb1, 1));
        mb1 = fmaxf(mb1, __shfl_xor_sync(0xffffffffu, mb1, 2));

        float mn0 = fmaxf(m0, mb0), mn1 = fmaxf(m1, mb1);
        float al0 = exp2f(m0 - mn0), al1 = exp2f(m1 - mn1);
        m0 = mn0; m1 = mn1;

        float rs0 = 0.f, rs1 = 0.f;
#pragma unroll
        for (int j = 0; j < 8; j++) {
            s[j][0] = exp2f(s[j][0] - mn0);
            s[j][1] = exp2f(s[j][1] - mn0);
            s[j][2] = exp2f(s[j][2] - mn1);
            s[j][3] = exp2f(s[j][3] - mn1);
            rs0 += s[j][0] + s[j][1];
            rs1 += s[j][2] + s[j][3];
        }
        rs0 += __shfl_xor_sync(0xffffffffu, rs0, 1);
        rs0 += __shfl_xor_sync(0xffffffffu, rs0, 2);
        rs1 += __shfl_xor_sync(0xffffffffu, rs1, 1);
        rs1 += __shfl_xor_sync(0xffffffffu, rs1, 2);
        l0 = l0 * al0 + rs0;
        l1 = l1 * al1 + rs1;

#pragma unroll
        for (int j = 0; j < 8; j++) {
            o[j][0] *= al0; o[j][1] *= al0;
            o[j][2] *= al1; o[j][3] *= al1;
        }

        // ---- O += P V (2-term: P*Vhi + P*Vlo) ----
#pragma unroll
        for (int jc = 0; jc < 4; jc++) {
            uint32_t ph[4];
            ph[0] = pack2h(s[2*jc][0],   s[2*jc][1]);
            ph[1] = pack2h(s[2*jc][2],   s[2*jc][3]);
            ph[2] = pack2h(s[2*jc+1][0], s[2*jc+1][1]);
            ph[3] = pack2h(s[2*jc+1][2], s[2*jc+1][3]);
#pragma unroll
            for (int fp = 0; fp < 4; fp++) {
                uint32_t off = ((fp * 16 + browB) * 36 + jc * 8 + bkB) * 4;
                uint32_t h0, h1, h2, h3, c0, c1, c2, c3;
                ldmatrix_x4(h0, h1, h2, h3, aVh + off);
                ldmatrix_x4(c0, c1, c2, c3, aVl + off);
                int jf = 2 * fp;
                mma16816(o[jf],   ph[0], ph[1], ph[2], ph[3], h0, h1);
                mma16816(o[jf],   ph[0], ph[1], ph[2], ph[3], c0, c1);
                mma16816(o[jf+1], ph[0], ph[1], ph[2], ph[3], h2, h3);
                mma16816(o[jf+1], ph[0], ph[1], ph[2], ph[3], c2, c3);
            }
        }
        __syncthreads();
    }

    // ---- epilogue: write fp16-split attn directly ----
    float inv0 = 1.f / l0, inv1 = 1.f / l1;
    {
        uint32_t* ahi = (uint32_t*)g_ahi;
        uint32_t* alo = (uint32_t*)g_alo;
        int r0 = nt * 128 + wid * 16 + gid;
        size_t base0 = (((size_t)b * CN + r0) * CC + h * CD) / 2;
        size_t base1 = base0 + 4 * CC;
#pragma unroll
        for (int jf = 0; jf < 8; jf++) {
            int colw = (jf * 8 + 2 * tig) / 2;
            uint32_t h0, l0w, h1, l1w;
            split2h(o[jf][0] * inv0, o[jf][1] * inv0, h0, l0w);
            split2h(o[jf][2] * inv1, o[jf][3] * inv1, h1, l1w);
            ahi[base0 + colw] = h0;  alo[base0 + colw] = l0w;
            ahi[base1 + colw] = h1;  alo[base1 + colw] = l1w;
        }
    }
}

// ----------------------------------------------------------------------------
// Launch
// ----------------------------------------------------------------------------
extern "C" void kernel_launch(void* const* d_in, const int* in_sizes, int n_in,
                              void* d_out, int out_size)
{
    const float* x     = (const float*)d_in[0];
    const float* ctx   = (const float*)d_in[1];
    const float* fc    = (const float*)d_in[2];
    const float* Wq    = (const float*)d_in[3];
    const float* Wkv   = (const float*)d_in[4];
    const float* Wproj = (const float*)d_in[5];
    const float* bproj = (const float*)d_in[6];
    float* out = (float*)d_out;

    float *q, *kvp;
    uint4 *ahi, *alo, *wh;
    cudaGetSymbolAddress((void**)&q,    g_q);
    cudaGetSymbolAddress((void**)&kvp,  g_kv);
    cudaGetSymbolAddress((void**)&ahi,  g_ahi);
    cudaGetSymbolAddress((void**)&alo,  g_alo);
    cudaGetSymbolAddress((void**)&wh,   g_wh);

    const __half* ah = (const __half*)ahi;
    const __half* al = (const __half*)alo;
    const __half* wp = (const __half*)wh;

    cudaFuncSetAttribute(flash_mma_kernel,
                         cudaFuncAttributeMaxDynamicSharedMemorySize, FLASH_SMEM);
    cudaFuncSetAttribute(gemm_fp16_kernel,
                         cudaFuncAttributeMaxDynamicSharedMemorySize, GEMM_SMEM);
    cudaFuncSetAttribute(gemm_kv_kernel,
                         cudaFuncAttributeMaxDynamicSharedMemorySize, GEMM_SMEM);

    const int actN8 = CB * CN * CC / 8;
    const int wN8   = CC * CC / 8;

    // 1) q = x @ Wq^T
    split_kernel<<<(actN8 + 255) / 256, 256>>>(x, ahi, alo, actN8);
    cvt_kernel<<<(wN8 + 255) / 256, 256>>>(Wq, wh, wN8);
    gemm_fp16_kernel<<<dim3(CC / 128, (CB * CN) / 128), 256, GEMM_SMEM>>>(
        ah, al, wp, q, CB * CN, CC, CC, nullptr);

    // 2) kv = context @ Wkv^T (K half: rope+fp16 fused; V half: fp32)
    split_kernel<<<(actN8 + 255) / 256, 256>>>(ctx, ahi, alo, actN8);
    cvt_kernel<<<(2 * wN8 + 255) / 256, 256>>>(Wkv, wh, 2 * wN8);
    gemm_kv_kernel<<<dim3((2 * CC) / 128, (CB * CM) / 128), 256, GEMM_SMEM>>>(
        ah, al, wp, kvp, CB * CM, 2 * CC, CC, fc);

    // 3) convert pre-pass: V split+transpose only
    conv_v_kernel<<<dim3(CM / 64, CH, CB), 256>>>();

    // 4) flash attention (Q-rope fused; writes fp16-split attn)
    flash_mma_kernel<<<dim3(CN / 128, CH, CB), 256, FLASH_SMEM>>>(q, fc);

    // 5) out = attn @ Wproj^T + bproj
    cvt_kernel<<<(wN8 + 255) / 256, 256>>>(Wproj, wh, wN8);
    gemm_fp16_kernel<<<dim3(CC / 128, (CB * CN) / 128), 256, GEMM_SMEM>>>(
        ah, al, wp, out, CB * CN, CC, CC, bproj);
}